// round 7
// baseline (speedup 1.0000x reference)
#include <cuda_runtime.h>
#include <cuda_bf16.h>
#include <cuda_fp16.h>
#include <math.h>

#define MAXN 100000
#define MAXE 1600000
#define DIN 128
#define DOUT 128
#define NHEAD 4
#define CDIM 32
#define NEG_SLOPE 0.2f
#define EPS 1e-16f

// Scratch (allocation-free: __device__ globals)
__device__ __half g_hh[MAXN * DOUT];    // projected features, fp16
__device__ float g_asrc[MAXN * NHEAD];
__device__ float g_adst[MAXN * NHEAD];
__device__ int g_deg[MAXN];
__device__ int g_pre[MAXN];
__device__ int g_rowptr[MAXN];
__device__ int g_cursor[MAXN];
__device__ int g_bsum[1024];
__device__ int g_col[MAXE];

__device__ __forceinline__ float lrelu(float v) {
    return v > 0.0f ? v : NEG_SLOPE * v;
}

__device__ __forceinline__ void tf32split(float v, unsigned& hi, unsigned& lo) {
    asm("cvt.rna.tf32.f32 %0, %1;" : "=r"(hi) : "f"(v));
    float r = v - __uint_as_float(hi);
    asm("cvt.rna.tf32.f32 %0, %1;" : "=r"(lo) : "f"(r));
}

__device__ __forceinline__ void mma8(float* c, const unsigned* a, const unsigned* b) {
    asm("mma.sync.aligned.m16n8k8.row.col.f32.tf32.tf32.f32 "
        "{%0,%1,%2,%3}, {%4,%5,%6,%7}, {%8,%9}, {%0,%1,%2,%3};"
        : "+f"(c[0]), "+f"(c[1]), "+f"(c[2]), "+f"(c[3])
        : "r"(a[0]), "r"(a[1]), "r"(a[2]), "r"(a[3]), "r"(b[0]), "r"(b[1]));
}

// ---------------------------------------------------------------------------
// GEMM h = x@W via 3xTF32 mma.sync + fused logits epilogue. h stored fp16.
#define SMS 132
__global__ __launch_bounds__(256, 1)
void gemm_mma_kernel(const float* __restrict__ x, const float* __restrict__ W,
                     const float* __restrict__ att_src, const float* __restrict__ att_dst,
                     __half* __restrict__ hh, float* __restrict__ asrc,
                     float* __restrict__ adst, int N) {
    extern __shared__ float smem[];
    float* xs = smem;              // [128][SMS]
    float* wT = smem + 128 * SMS;  // transposed W

    int tid = threadIdx.x;
    int lane = tid & 31;
    int w = tid >> 5;
    int g = lane >> 2;
    int t = lane & 3;
    int rgrp = w >> 2;
    int head = w & 3;
    int rbase_blk = blockIdx.x * 128;

    #pragma unroll
    for (int i = 0; i < 64; i++) {
        int id = tid + i * 256;
        int r = id >> 7, c = id & 127;
        int gr = rbase_blk + r;
        xs[r * SMS + c] = (gr < N) ? x[(long)gr * DIN + c] : 0.0f;
        int k = id >> 7, n = id & 127;
        wT[n * SMS + k] = W[k * DOUT + n];
    }
    __syncthreads();

    float c_acc[4][4][4];
    #pragma unroll
    for (int mi = 0; mi < 4; mi++)
        #pragma unroll
        for (int ni = 0; ni < 4; ni++)
            #pragma unroll
            for (int f = 0; f < 4; f++) c_acc[mi][ni][f] = 0.0f;

    #pragma unroll 1
    for (int kk = 0; kk < DIN; kk += 8) {
        unsigned bh[4][2], bl[4][2];
        #pragma unroll
        for (int ni = 0; ni < 4; ni++) {
            int col = head * 32 + ni * 8 + g;
            float b0 = wT[col * SMS + kk + t];
            float b1 = wT[col * SMS + kk + t + 4];
            tf32split(b0, bh[ni][0], bl[ni][0]);
            tf32split(b1, bh[ni][1], bl[ni][1]);
        }
        #pragma unroll
        for (int mi = 0; mi < 4; mi++) {
            int ar = rgrp * 64 + mi * 16 + g;
            float a0 = xs[ar * SMS + kk + t];
            float a1 = xs[(ar + 8) * SMS + kk + t];
            float a2 = xs[ar * SMS + kk + t + 4];
            float a3 = xs[(ar + 8) * SMS + kk + t + 4];
            unsigned ah[4], al[4];
            tf32split(a0, ah[0], al[0]);
            tf32split(a1, ah[1], al[1]);
            tf32split(a2, ah[2], al[2]);
            tf32split(a3, ah[3], al[3]);
            #pragma unroll
            for (int ni = 0; ni < 4; ni++) {
                mma8(c_acc[mi][ni], ah, bh[ni]);
                mma8(c_acc[mi][ni], ah, bl[ni]);
                mma8(c_acc[mi][ni], al, bh[ni]);
            }
        }
    }

    float asv[4][2], adv[4][2];
    #pragma unroll
    for (int ni = 0; ni < 4; ni++)
        #pragma unroll
        for (int j = 0; j < 2; j++) {
            int lcol = ni * 8 + 2 * t + j;
            asv[ni][j] = att_src[head * CDIM + lcol];
            adv[ni][j] = att_dst[head * CDIM + lcol];
        }

    #pragma unroll
    for (int mi = 0; mi < 4; mi++) {
        int rowA = rbase_blk + rgrp * 64 + mi * 16 + g;
        int rowB = rowA + 8;
        float sA = 0.f, sB = 0.f, dA = 0.f, dB = 0.f;
        #pragma unroll
        for (int ni = 0; ni < 4; ni++) {
            float c0 = c_acc[mi][ni][0], c1 = c_acc[mi][ni][1];
            float c2 = c_acc[mi][ni][2], c3 = c_acc[mi][ni][3];
            sA += c0 * asv[ni][0] + c1 * asv[ni][1];
            dA += c0 * adv[ni][0] + c1 * adv[ni][1];
            sB += c2 * asv[ni][0] + c3 * asv[ni][1];
            dB += c2 * adv[ni][0] + c3 * adv[ni][1];
            long colbase = head * 32 + ni * 8 + 2 * t;
            if (rowA < N) *(__half2*)(hh + (long)rowA * DOUT + colbase) = __floats2half2_rn(c0, c1);
            if (rowB < N) *(__half2*)(hh + (long)rowB * DOUT + colbase) = __floats2half2_rn(c2, c3);
        }
        #pragma unroll
        for (int o = 1; o <= 2; o <<= 1) {
            sA += __shfl_xor_sync(0xffffffffu, sA, o);
            sB += __shfl_xor_sync(0xffffffffu, sB, o);
            dA += __shfl_xor_sync(0xffffffffu, dA, o);
            dB += __shfl_xor_sync(0xffffffffu, dB, o);
        }
        if (t == 0) {
            if (rowA < N) { asrc[rowA * 4 + head] = sA; adst[rowA * 4 + head] = dA; }
            if (rowB < N) { asrc[rowB * 4 + head] = sB; adst[rowB * 4 + head] = dB; }
        }
    }
}

// ---------------------------------------------------------------------------
// CSR build over the E real edges (self loops inline in agg)
__global__ void hist_kernel(const int* __restrict__ ei, int E, int* __restrict__ deg) {
    int i = blockIdx.x * blockDim.x + threadIdx.x;
    if (i >= E) return;
    atomicAdd(&deg[ei[E + i]], 1);
}

__global__ void scan_block(const int* __restrict__ deg, int* __restrict__ pre,
                           int* __restrict__ bsum, int N) {
    __shared__ int tmp[2][1024];
    int t = threadIdx.x;
    int gidx = blockIdx.x * 1024 + t;
    int v = (gidx < N) ? deg[gidx] : 0;
    tmp[0][t] = v;
    __syncthreads();
    int pi = 0;
    for (int off = 1; off < 1024; off <<= 1) {
        int val = tmp[pi][t];
        if (t >= off) val += tmp[pi][t - off];
        tmp[pi ^ 1][t] = val;
        pi ^= 1;
        __syncthreads();
    }
    int inc = tmp[pi][t];
    if (gidx < N) pre[gidx] = inc - v;
    if (t == 1023) bsum[blockIdx.x] = inc;
}

__global__ void scan_add_fused(const int* __restrict__ pre, const int* __restrict__ bsum,
                               int* __restrict__ rowptr, int* __restrict__ cursor,
                               int N, int NB) {
    __shared__ int sb[1024];
    int t = threadIdx.x;
    sb[t] = (t < NB) ? bsum[t] : 0;
    __syncthreads();
    for (int off = 1; off < 1024; off <<= 1) {
        int v = sb[t];
        int a = (t >= off) ? sb[t - off] : 0;
        __syncthreads();
        sb[t] = v + a;
        __syncthreads();
    }
    int gidx = blockIdx.x * 1024 + t;
    if (gidx < N) {
        int boff = (blockIdx.x == 0) ? 0 : sb[blockIdx.x - 1];
        int v = pre[gidx] + boff;
        rowptr[gidx] = v;
        cursor[gidx] = v;
    }
}

__global__ void scatter_kernel(const int* __restrict__ ei, int E,
                               int* __restrict__ cursor, int* __restrict__ col) {
    int i = blockIdx.x * blockDim.x + threadIdx.x;
    if (i >= E) return;
    int s = ei[i], d = ei[E + i];
    int pos = atomicAdd(&cursor[d], 1);
    col[pos] = s;
}

// ---------------------------------------------------------------------------
// Fused softmax+aggregate, one warp per dst node.
// Chunked: 32 col indices loaded coalesced per chunk; weights computed
// lane-parallel (float4 asrc + 4 exps per edge by one lane); gather loop reads
// idx+weight from smem so all h-gather addresses are available (high MLP).
__global__ __launch_bounds__(256)
void agg_kernel(const int* __restrict__ col, const int* __restrict__ rowptr,
                const int* __restrict__ deg,
                const float* __restrict__ asrc, const float* __restrict__ adst,
                const __half* __restrict__ hh, const float* __restrict__ bias,
                float* __restrict__ out, int N) {
    __shared__ int s_idx[8][32];
    __shared__ float4 s_w[8][32];

    int gtid = blockIdx.x * blockDim.x + threadIdx.x;
    int w = gtid >> 5;
    int lane = threadIdx.x & 31;
    int wid = (threadIdx.x >> 5) & 7;
    if (w >= N) return;

    int start = rowptr[w];
    int cnt = deg[w];
    int myhead = lane >> 3;
    float4 ad4 = *(const float4*)(adst + w * 4);

    // Self loop
    float4 as0 = *(const float4*)(asrc + w * 4);
    float wgt0 = __expf(lrelu(((const float*)&as0)[myhead] + ((const float*)&ad4)[myhead]));
    float ssum = wgt0;
    uint2 raw0 = *reinterpret_cast<const uint2*>(hh + (long)w * DOUT + lane * 4);
    float2 f01 = __half22float2(*reinterpret_cast<__half2*>(&raw0.x));
    float2 f23 = __half22float2(*reinterpret_cast<__half2*>(&raw0.y));
    float a0 = f01.x * wgt0, a1 = f01.y * wgt0, a2 = f23.x * wgt0, a3 = f23.y * wgt0;

    for (int base = 0; base < cnt; base += 32) {
        int j = base + lane;
        int idx = 0;
        float4 wv = make_float4(0.f, 0.f, 0.f, 0.f);
        if (j < cnt) {
            idx = __ldg(col + start + j);                 // coalesced
            float4 as = *(const float4*)(asrc + idx * 4); // 16B per edge
            wv.x = __expf(lrelu(as.x + ad4.x));
            wv.y = __expf(lrelu(as.y + ad4.y));
            wv.z = __expf(lrelu(as.z + ad4.z));
            wv.w = __expf(lrelu(as.w + ad4.w));
        }
        s_idx[wid][lane] = idx;
        s_w[wid][lane] = wv;
        __syncwarp();

        int lim = min(cnt - base, 32);
        #pragma unroll 4
        for (int jj = 0; jj < lim; jj++) {
            int src = s_idx[wid][jj];                       // LDS broadcast
            float wgt = ((const float*)&s_w[wid][jj])[myhead];
            ssum += wgt;
            uint2 raw = *reinterpret_cast<const uint2*>(hh + (long)src * DOUT + lane * 4);
            float2 g01 = __half22float2(*reinterpret_cast<__half2*>(&raw.x));
            float2 g23 = __half22float2(*reinterpret_cast<__half2*>(&raw.y));
            a0 = fmaf(g01.x, wgt, a0);
            a1 = fmaf(g01.y, wgt, a1);
            a2 = fmaf(g23.x, wgt, a2);
            a3 = fmaf(g23.y, wgt, a3);
        }
        __syncwarp();
    }

    float inv = 1.0f / (ssum + EPS);
    float4 b4 = *(const float4*)(bias + lane * 4);
    float4 o4 = make_float4(fmaf(a0, inv, b4.x), fmaf(a1, inv, b4.y),
                            fmaf(a2, inv, b4.z), fmaf(a3, inv, b4.w));
    *(float4*)(out + (long)w * DOUT + lane * 4) = o4;
}

// ---------------------------------------------------------------------------
extern "C" void kernel_launch(void* const* d_in, const int* in_sizes, int n_in,
                              void* d_out, int out_size) {
    const float* x = (const float*)d_in[0];
    const int* ei = (const int*)d_in[1];
    const float* W = (const float*)d_in[2];
    const float* att_src = (const float*)d_in[3];
    const float* att_dst = (const float*)d_in[4];
    const float* bias = (const float*)d_in[5];
    float* out = (float*)d_out;

    int N = in_sizes[0] / DIN;
    int E = in_sizes[1] / 2;
    int NB = (N + 1023) / 1024;

    __half* hh;
    float *asrc, *adst;
    int *deg, *pre, *rowptr, *cursor, *bsum, *colp;
    cudaGetSymbolAddress((void**)&hh, g_hh);
    cudaGetSymbolAddress((void**)&asrc, g_asrc);
    cudaGetSymbolAddress((void**)&adst, g_adst);
    cudaGetSymbolAddress((void**)&deg, g_deg);
    cudaGetSymbolAddress((void**)&pre, g_pre);
    cudaGetSymbolAddress((void**)&rowptr, g_rowptr);
    cudaGetSymbolAddress((void**)&cursor, g_cursor);
    cudaGetSymbolAddress((void**)&bsum, g_bsum);
    cudaGetSymbolAddress((void**)&colp, g_col);

    int smem_bytes = 2 * 128 * SMS * sizeof(float);
    cudaFuncSetAttribute(gemm_mma_kernel, cudaFuncAttributeMaxDynamicSharedMemorySize, smem_bytes);

    int thr = 256;

    cudaStream_t s2;
    cudaStreamCreateWithFlags(&s2, cudaStreamNonBlocking);
    cudaEvent_t evFork, evJoin;
    cudaEventCreateWithFlags(&evFork, cudaEventDisableTiming);
    cudaEventCreateWithFlags(&evJoin, cudaEventDisableTiming);

    cudaEventRecord(evFork, 0);
    cudaStreamWaitEvent(s2, evFork, 0);

    // Side stream: CSR build over E edges
    cudaMemsetAsync(deg, 0, N * sizeof(int), s2);
    hist_kernel<<<(E + thr - 1) / thr, thr, 0, s2>>>(ei, E, deg);
    scan_block<<<NB, 1024, 0, s2>>>(deg, pre, bsum, N);
    scan_add_fused<<<NB, 1024, 0, s2>>>(pre, bsum, rowptr, cursor, N, NB);
    scatter_kernel<<<(E + thr - 1) / thr, thr, 0, s2>>>(ei, E, cursor, colp);
    cudaEventRecord(evJoin, s2);

    // Main stream: GEMM + fused logits (fp16 h output)
    gemm_mma_kernel<<<(N + 127) / 128, 256, smem_bytes>>>(x, W, att_src, att_dst, hh, asrc, adst, N);

    cudaStreamWaitEvent(0, evJoin, 0);
    agg_kernel<<<(N * 32 + thr - 1) / thr, thr>>>(colp, rowptr, deg, asrc, adst, hh, bias, out, N);

    cudaEventDestroy(evFork);
    cudaEventDestroy(evJoin);
    cudaStreamDestroy(s2);
}

// round 8
// speedup vs baseline: 1.0459x; 1.0459x over previous
#include <cuda_runtime.h>
#include <cuda_bf16.h>
#include <cuda_fp16.h>
#include <math.h>

#define MAXN 100000
#define MAXE 1600000
#define DIN 128
#define DOUT 128
#define NHEAD 4
#define CDIM 32
#define NEG_SLOPE 0.2f
#define EPS 1e-16f

// Scratch (allocation-free: __device__ globals)
__device__ __half g_hh[MAXN * DOUT];    // projected features, fp16
__device__ float g_asrc[MAXN * NHEAD];
__device__ float g_adst[MAXN * NHEAD];
__device__ int g_deg[MAXN];
__device__ int g_pre[MAXN];
__device__ int g_rowptr[MAXN];
__device__ int g_cursor[MAXN];
__device__ int g_bsum[1024];
__device__ int g_col[MAXE];

__device__ __forceinline__ float lrelu(float v) {
    return v > 0.0f ? v : NEG_SLOPE * v;
}

__device__ __forceinline__ void tf32split(float v, unsigned& hi, unsigned& lo) {
    asm("cvt.rna.tf32.f32 %0, %1;" : "=r"(hi) : "f"(v));
    float r = v - __uint_as_float(hi);
    asm("cvt.rna.tf32.f32 %0, %1;" : "=r"(lo) : "f"(r));
}

__device__ __forceinline__ void mma8(float* c, const unsigned* a, const unsigned* b) {
    asm("mma.sync.aligned.m16n8k8.row.col.f32.tf32.tf32.f32 "
        "{%0,%1,%2,%3}, {%4,%5,%6,%7}, {%8,%9}, {%0,%1,%2,%3};"
        : "+f"(c[0]), "+f"(c[1]), "+f"(c[2]), "+f"(c[3])
        : "r"(a[0]), "r"(a[1]), "r"(a[2]), "r"(a[3]), "r"(b[0]), "r"(b[1]));
}

// ---------------------------------------------------------------------------
// GEMM h = x@W via 3xTF32 mma.sync + fused logits epilogue. h stored fp16.
#define SMS 132
__global__ __launch_bounds__(256, 1)
void gemm_mma_kernel(const float* __restrict__ x, const float* __restrict__ W,
                     const float* __restrict__ att_src, const float* __restrict__ att_dst,
                     __half* __restrict__ hh, float* __restrict__ asrc,
                     float* __restrict__ adst, int N) {
    extern __shared__ float smem[];
    float* xs = smem;              // [128][SMS]
    float* wT = smem + 128 * SMS;  // transposed W

    int tid = threadIdx.x;
    int lane = tid & 31;
    int w = tid >> 5;
    int g = lane >> 2;
    int t = lane & 3;
    int rgrp = w >> 2;
    int head = w & 3;
    int rbase_blk = blockIdx.x * 128;

    #pragma unroll
    for (int i = 0; i < 64; i++) {
        int id = tid + i * 256;
        int r = id >> 7, c = id & 127;
        int gr = rbase_blk + r;
        xs[r * SMS + c] = (gr < N) ? x[(long)gr * DIN + c] : 0.0f;
        int k = id >> 7, n = id & 127;
        wT[n * SMS + k] = W[k * DOUT + n];
    }
    __syncthreads();

    float c_acc[4][4][4];
    #pragma unroll
    for (int mi = 0; mi < 4; mi++)
        #pragma unroll
        for (int ni = 0; ni < 4; ni++)
            #pragma unroll
            for (int f = 0; f < 4; f++) c_acc[mi][ni][f] = 0.0f;

    #pragma unroll 1
    for (int kk = 0; kk < DIN; kk += 8) {
        unsigned bh[4][2], bl[4][2];
        #pragma unroll
        for (int ni = 0; ni < 4; ni++) {
            int col = head * 32 + ni * 8 + g;
            float b0 = wT[col * SMS + kk + t];
            float b1 = wT[col * SMS + kk + t + 4];
            tf32split(b0, bh[ni][0], bl[ni][0]);
            tf32split(b1, bh[ni][1], bl[ni][1]);
        }
        #pragma unroll
        for (int mi = 0; mi < 4; mi++) {
            int ar = rgrp * 64 + mi * 16 + g;
            float a0 = xs[ar * SMS + kk + t];
            float a1 = xs[(ar + 8) * SMS + kk + t];
            float a2 = xs[ar * SMS + kk + t + 4];
            float a3 = xs[(ar + 8) * SMS + kk + t + 4];
            unsigned ah[4], al[4];
            tf32split(a0, ah[0], al[0]);
            tf32split(a1, ah[1], al[1]);
            tf32split(a2, ah[2], al[2]);
            tf32split(a3, ah[3], al[3]);
            #pragma unroll
            for (int ni = 0; ni < 4; ni++) {
                mma8(c_acc[mi][ni], ah, bh[ni]);
                mma8(c_acc[mi][ni], ah, bl[ni]);
                mma8(c_acc[mi][ni], al, bh[ni]);
            }
        }
    }

    float asv[4][2], adv[4][2];
    #pragma unroll
    for (int ni = 0; ni < 4; ni++)
        #pragma unroll
        for (int j = 0; j < 2; j++) {
            int lcol = ni * 8 + 2 * t + j;
            asv[ni][j] = att_src[head * CDIM + lcol];
            adv[ni][j] = att_dst[head * CDIM + lcol];
        }

    #pragma unroll
    for (int mi = 0; mi < 4; mi++) {
        int rowA = rbase_blk + rgrp * 64 + mi * 16 + g;
        int rowB = rowA + 8;
        float sA = 0.f, sB = 0.f, dA = 0.f, dB = 0.f;
        #pragma unroll
        for (int ni = 0; ni < 4; ni++) {
            float c0 = c_acc[mi][ni][0], c1 = c_acc[mi][ni][1];
            float c2 = c_acc[mi][ni][2], c3 = c_acc[mi][ni][3];
            sA += c0 * asv[ni][0] + c1 * asv[ni][1];
            dA += c0 * adv[ni][0] + c1 * adv[ni][1];
            sB += c2 * asv[ni][0] + c3 * asv[ni][1];
            dB += c2 * adv[ni][0] + c3 * adv[ni][1];
            long colbase = head * 32 + ni * 8 + 2 * t;
            if (rowA < N) *(__half2*)(hh + (long)rowA * DOUT + colbase) = __floats2half2_rn(c0, c1);
            if (rowB < N) *(__half2*)(hh + (long)rowB * DOUT + colbase) = __floats2half2_rn(c2, c3);
        }
        #pragma unroll
        for (int o = 1; o <= 2; o <<= 1) {
            sA += __shfl_xor_sync(0xffffffffu, sA, o);
            sB += __shfl_xor_sync(0xffffffffu, sB, o);
            dA += __shfl_xor_sync(0xffffffffu, dA, o);
            dB += __shfl_xor_sync(0xffffffffu, dB, o);
        }
        if (t == 0) {
            if (rowA < N) { asrc[rowA * 4 + head] = sA; adst[rowA * 4 + head] = dA; }
            if (rowB < N) { asrc[rowB * 4 + head] = sB; adst[rowB * 4 + head] = dB; }
        }
    }
}

// ---------------------------------------------------------------------------
// CSR build over the E real edges (self loops inline in agg).
// 4 edges per thread, vectorized int4 reads.
__global__ void hist_kernel(const int* __restrict__ ei, int E, int* __restrict__ deg) {
    int i = (blockIdx.x * blockDim.x + threadIdx.x) * 4;
    if (i + 3 < E) {
        int4 d4 = *(const int4*)(ei + E + i);
        atomicAdd(&deg[d4.x], 1);
        atomicAdd(&deg[d4.y], 1);
        atomicAdd(&deg[d4.z], 1);
        atomicAdd(&deg[d4.w], 1);
    } else {
        for (int k = i; k < E; k++) atomicAdd(&deg[ei[E + k]], 1);
    }
}

__global__ void scan_block(const int* __restrict__ deg, int* __restrict__ pre,
                           int* __restrict__ bsum, int N) {
    __shared__ int tmp[2][1024];
    int t = threadIdx.x;
    int gidx = blockIdx.x * 1024 + t;
    int v = (gidx < N) ? deg[gidx] : 0;
    tmp[0][t] = v;
    __syncthreads();
    int pi = 0;
    for (int off = 1; off < 1024; off <<= 1) {
        int val = tmp[pi][t];
        if (t >= off) val += tmp[pi][t - off];
        tmp[pi ^ 1][t] = val;
        pi ^= 1;
        __syncthreads();
    }
    int inc = tmp[pi][t];
    if (gidx < N) pre[gidx] = inc - v;
    if (t == 1023) bsum[blockIdx.x] = inc;
}

__global__ void scan_add_fused(const int* __restrict__ pre, const int* __restrict__ bsum,
                               int* __restrict__ rowptr, int* __restrict__ cursor,
                               int N, int NB) {
    __shared__ int sb[1024];
    int t = threadIdx.x;
    sb[t] = (t < NB) ? bsum[t] : 0;
    __syncthreads();
    for (int off = 1; off < 1024; off <<= 1) {
        int v = sb[t];
        int a = (t >= off) ? sb[t - off] : 0;
        __syncthreads();
        sb[t] = v + a;
        __syncthreads();
    }
    int gidx = blockIdx.x * 1024 + t;
    if (gidx < N) {
        int boff = (blockIdx.x == 0) ? 0 : sb[blockIdx.x - 1];
        int v = pre[gidx] + boff;
        rowptr[gidx] = v;
        cursor[gidx] = v;
    }
}

__global__ void scatter_kernel(const int* __restrict__ ei, int E,
                               int* __restrict__ cursor, int* __restrict__ col) {
    int i = (blockIdx.x * blockDim.x + threadIdx.x) * 4;
    if (i + 3 < E) {
        int4 s4 = *(const int4*)(ei + i);
        int4 d4 = *(const int4*)(ei + E + i);
        int p0 = atomicAdd(&cursor[d4.x], 1);
        int p1 = atomicAdd(&cursor[d4.y], 1);
        int p2 = atomicAdd(&cursor[d4.z], 1);
        int p3 = atomicAdd(&cursor[d4.w], 1);
        col[p0] = s4.x;
        col[p1] = s4.y;
        col[p2] = s4.z;
        col[p3] = s4.w;
    } else {
        for (int k = i; k < E; k++) {
            int pos = atomicAdd(&cursor[ei[E + k]], 1);
            col[pos] = ei[k];
        }
    }
}

// ---------------------------------------------------------------------------
// Fused softmax+aggregate, one warp per dst node, HALF-WARP per edge.
// fp16 h row = 256B = 16 lanes x 16B; lanes 0-15 even edges, 16-31 odd edges.
// Each lane owns 8 features (one head). Cross-half merge via shfl at the end.
__global__ __launch_bounds__(256)
void agg_kernel(const int* __restrict__ col, const int* __restrict__ rowptr,
                const int* __restrict__ deg,
                const float* __restrict__ asrc, const float* __restrict__ adst,
                const __half* __restrict__ hh, const float* __restrict__ bias,
                float* __restrict__ out, int N) {
    int gtid = blockIdx.x * blockDim.x + threadIdx.x;
    int w = gtid >> 5;
    int lane = threadIdx.x & 31;
    if (w >= N) return;

    int half = lane >> 4;   // 0 or 1
    int L = lane & 15;      // lane within half
    int myhead = L >> 2;    // 4 lanes per head; lane owns features [L*8, L*8+8)

    int start = rowptr[w];
    int cnt = deg[w];
    float adh = __ldg(adst + w * 4 + myhead);

    float acc[8];
    #pragma unroll
    for (int k = 0; k < 8; k++) acc[k] = 0.0f;
    float ssum = 0.0f;

    // Self loop: half 0 only
    if (half == 0) {
        float wgt0 = __expf(lrelu(__ldg(asrc + w * 4 + myhead) + adh));
        ssum = wgt0;
        uint4 raw = *reinterpret_cast<const uint4*>(hh + (long)w * DOUT + L * 8);
        const __half2* h2 = reinterpret_cast<const __half2*>(&raw);
        #pragma unroll
        for (int k = 0; k < 4; k++) {
            float2 f = __half22float2(h2[k]);
            acc[2 * k] = f.x * wgt0;
            acc[2 * k + 1] = f.y * wgt0;
        }
    }

    // Each half processes alternating edges
    #pragma unroll 4
    for (int j = half; j < cnt; j += 2) {
        int src = __ldg(col + start + j);   // uniform within half
        float e = lrelu(__ldg(asrc + src * 4 + myhead) + adh);
        float wgt = __expf(e);
        ssum += wgt;
        uint4 raw = *reinterpret_cast<const uint4*>(hh + (long)src * DOUT + L * 8);
        const __half2* h2 = reinterpret_cast<const __half2*>(&raw);
        #pragma unroll
        for (int k = 0; k < 4; k++) {
            float2 f = __half22float2(h2[k]);
            acc[2 * k] = fmaf(f.x, wgt, acc[2 * k]);
            acc[2 * k + 1] = fmaf(f.y, wgt, acc[2 * k + 1]);
        }
    }

    // Merge odd-edge half into even half
    ssum += __shfl_down_sync(0xffffffffu, ssum, 16);
    #pragma unroll
    for (int k = 0; k < 8; k++)
        acc[k] += __shfl_down_sync(0xffffffffu, acc[k], 16);

    if (half == 0) {
        float inv = 1.0f / (ssum + EPS);
        float4 b0 = *(const float4*)(bias + L * 8);
        float4 b1 = *(const float4*)(bias + L * 8 + 4);
        float4 o0 = make_float4(fmaf(acc[0], inv, b0.x), fmaf(acc[1], inv, b0.y),
                                fmaf(acc[2], inv, b0.z), fmaf(acc[3], inv, b0.w));
        float4 o1 = make_float4(fmaf(acc[4], inv, b1.x), fmaf(acc[5], inv, b1.y),
                                fmaf(acc[6], inv, b1.z), fmaf(acc[7], inv, b1.w));
        *(float4*)(out + (long)w * DOUT + L * 8) = o0;
        *(float4*)(out + (long)w * DOUT + L * 8 + 4) = o1;
    }
}

// ---------------------------------------------------------------------------
extern "C" void kernel_launch(void* const* d_in, const int* in_sizes, int n_in,
                              void* d_out, int out_size) {
    const float* x = (const float*)d_in[0];
    const int* ei = (const int*)d_in[1];
    const float* W = (const float*)d_in[2];
    const float* att_src = (const float*)d_in[3];
    const float* att_dst = (const float*)d_in[4];
    const float* bias = (const float*)d_in[5];
    float* out = (float*)d_out;

    int N = in_sizes[0] / DIN;
    int E = in_sizes[1] / 2;
    int NB = (N + 1023) / 1024;
    int E4 = (E + 3) / 4;

    __half* hh;
    float *asrc, *adst;
    int *deg, *pre, *rowptr, *cursor, *bsum, *colp;
    cudaGetSymbolAddress((void**)&hh, g_hh);
    cudaGetSymbolAddress((void**)&asrc, g_asrc);
    cudaGetSymbolAddress((void**)&adst, g_adst);
    cudaGetSymbolAddress((void**)&deg, g_deg);
    cudaGetSymbolAddress((void**)&pre, g_pre);
    cudaGetSymbolAddress((void**)&rowptr, g_rowptr);
    cudaGetSymbolAddress((void**)&cursor, g_cursor);
    cudaGetSymbolAddress((void**)&bsum, g_bsum);
    cudaGetSymbolAddress((void**)&colp, g_col);

    int smem_bytes = 2 * 128 * SMS * sizeof(float);
    cudaFuncSetAttribute(gemm_mma_kernel, cudaFuncAttributeMaxDynamicSharedMemorySize, smem_bytes);

    int thr = 256;

    cudaStream_t s2;
    cudaStreamCreateWithFlags(&s2, cudaStreamNonBlocking);
    cudaEvent_t evFork, evJoin;
    cudaEventCreateWithFlags(&evFork, cudaEventDisableTiming);
    cudaEventCreateWithFlags(&evJoin, cudaEventDisableTiming);

    cudaEventRecord(evFork, 0);
    cudaStreamWaitEvent(s2, evFork, 0);

    // Side stream: CSR build over E edges
    cudaMemsetAsync(deg, 0, N * sizeof(int), s2);
    hist_kernel<<<(E4 + thr - 1) / thr, thr, 0, s2>>>(ei, E, deg);
    scan_block<<<NB, 1024, 0, s2>>>(deg, pre, bsum, N);
    scan_add_fused<<<NB, 1024, 0, s2>>>(pre, bsum, rowptr, cursor, N, NB);
    scatter_kernel<<<(E4 + thr - 1) / thr, thr, 0, s2>>>(ei, E, cursor, colp);
    cudaEventRecord(evJoin, s2);

    // Main stream: GEMM + fused logits (fp16 h output)
    gemm_mma_kernel<<<(N + 127) / 128, 256, smem_bytes>>>(x, W, att_src, att_dst, hh, asrc, adst, N);

    cudaStreamWaitEvent(0, evJoin, 0);
    agg_kernel<<<(N * 32 + thr - 1) / thr, thr>>>(colp, rowptr, deg, asrc, adst, hh, bias, out, N);

    cudaEventDestroy(evFork);
    cudaEventDestroy(evJoin);
    cudaStreamDestroy(s2);
}

// round 9
// speedup vs baseline: 1.0989x; 1.0507x over previous
#include <cuda_runtime.h>
#include <cuda_bf16.h>
#include <cuda_fp16.h>
#include <math.h>

#define MAXN 100000
#define MAXE 1600000
#define DIN 128
#define DOUT 128
#define NHEAD 4
#define CDIM 32
#define NEG_SLOPE 0.2f
#define EPS 1e-16f

// Scratch (allocation-free: __device__ globals)
__device__ __half g_hh[MAXN * DOUT];    // projected features, fp16
__device__ float g_asrc[MAXN * NHEAD];
__device__ float g_adst[MAXN * NHEAD];
__device__ int g_deg[MAXN];
__device__ int g_pre[MAXN];
__device__ int g_rowptr[MAXN];
__device__ int g_cursor[MAXN];
__device__ int g_bsum[1024];
__device__ int g_col[MAXE];

__device__ __forceinline__ float lrelu(float v) {
    return v > 0.0f ? v : NEG_SLOPE * v;
}

__device__ __forceinline__ void tf32split(float v, unsigned& hi, unsigned& lo) {
    asm("cvt.rna.tf32.f32 %0, %1;" : "=r"(hi) : "f"(v));
    float r = v - __uint_as_float(hi);
    asm("cvt.rna.tf32.f32 %0, %1;" : "=r"(lo) : "f"(r));
}

__device__ __forceinline__ void mma8(float* c, const unsigned* a, const unsigned* b) {
    asm("mma.sync.aligned.m16n8k8.row.col.f32.tf32.tf32.f32 "
        "{%0,%1,%2,%3}, {%4,%5,%6,%7}, {%8,%9}, {%0,%1,%2,%3};"
        : "+f"(c[0]), "+f"(c[1]), "+f"(c[2]), "+f"(c[3])
        : "r"(a[0]), "r"(a[1]), "r"(a[2]), "r"(a[3]), "r"(b[0]), "r"(b[1]));
}

// ---------------------------------------------------------------------------
// GEMM h = x@W via 3xTF32 mma.sync + fused logits epilogue. h stored fp16.
// Staging: both tiles row-major, float4 vectorized. B fragments read from the
// row-major W tile (values only; at worst 2-way LDS conflicts).
#define SMS 132
__global__ __launch_bounds__(256, 1)
void gemm_mma_kernel(const float* __restrict__ x, const float* __restrict__ W,
                     const float* __restrict__ att_src, const float* __restrict__ att_dst,
                     __half* __restrict__ hh, float* __restrict__ asrc,
                     float* __restrict__ adst, int N) {
    extern __shared__ float smem[];
    float* xs = smem;              // [128][SMS] x tile, row-major
    float* wX = smem + 128 * SMS;  // [128][SMS] W tile, row-major (wX[k][n])

    int tid = threadIdx.x;
    int lane = tid & 31;
    int w = tid >> 5;
    int g = lane >> 2;
    int t = lane & 3;
    int rgrp = w >> 2;
    int head = w & 3;
    int rbase_blk = blockIdx.x * 128;

    // Vectorized staging: 4096 float4 per tile, 16 per thread.
    #pragma unroll
    for (int i = 0; i < 16; i++) {
        int id = tid + i * 256;          // 0..4095
        int r = id >> 5;                 // row 0..127
        int c4 = id & 31;                // float4 col 0..31
        int gr = rbase_blk + r;
        float4 xv = (gr < N) ? *(const float4*)(x + (long)gr * DIN + c4 * 4)
                             : make_float4(0.f, 0.f, 0.f, 0.f);
        *(float4*)(xs + r * SMS + c4 * 4) = xv;
        float4 wv = *(const float4*)(W + r * DOUT + c4 * 4);   // r = k here
        *(float4*)(wX + r * SMS + c4 * 4) = wv;
    }
    __syncthreads();

    float c_acc[4][4][4];
    #pragma unroll
    for (int mi = 0; mi < 4; mi++)
        #pragma unroll
        for (int ni = 0; ni < 4; ni++)
            #pragma unroll
            for (int f = 0; f < 4; f++) c_acc[mi][ni][f] = 0.0f;

    #pragma unroll 1
    for (int kk = 0; kk < DIN; kk += 8) {
        unsigned bh[4][2], bl[4][2];
        #pragma unroll
        for (int ni = 0; ni < 4; ni++) {
            int col = head * 32 + ni * 8 + g;
            float b0 = wX[(kk + t) * SMS + col];
            float b1 = wX[(kk + t + 4) * SMS + col];
            tf32split(b0, bh[ni][0], bl[ni][0]);
            tf32split(b1, bh[ni][1], bl[ni][1]);
        }
        #pragma unroll
        for (int mi = 0; mi < 4; mi++) {
            int ar = rgrp * 64 + mi * 16 + g;
            float a0 = xs[ar * SMS + kk + t];
            float a1 = xs[(ar + 8) * SMS + kk + t];
            float a2 = xs[ar * SMS + kk + t + 4];
            float a3 = xs[(ar + 8) * SMS + kk + t + 4];
            unsigned ah[4], al[4];
            tf32split(a0, ah[0], al[0]);
            tf32split(a1, ah[1], al[1]);
            tf32split(a2, ah[2], al[2]);
            tf32split(a3, ah[3], al[3]);
            #pragma unroll
            for (int ni = 0; ni < 4; ni++) {
                mma8(c_acc[mi][ni], ah, bh[ni]);
                mma8(c_acc[mi][ni], ah, bl[ni]);
                mma8(c_acc[mi][ni], al, bh[ni]);
            }
        }
    }

    float asv[4][2], adv[4][2];
    #pragma unroll
    for (int ni = 0; ni < 4; ni++)
        #pragma unroll
        for (int j = 0; j < 2; j++) {
            int lcol = ni * 8 + 2 * t + j;
            asv[ni][j] = att_src[head * CDIM + lcol];
            adv[ni][j] = att_dst[head * CDIM + lcol];
        }

    #pragma unroll
    for (int mi = 0; mi < 4; mi++) {
        int rowA = rbase_blk + rgrp * 64 + mi * 16 + g;
        int rowB = rowA + 8;
        float sA = 0.f, sB = 0.f, dA = 0.f, dB = 0.f;
        #pragma unroll
        for (int ni = 0; ni < 4; ni++) {
            float c0 = c_acc[mi][ni][0], c1 = c_acc[mi][ni][1];
            float c2 = c_acc[mi][ni][2], c3 = c_acc[mi][ni][3];
            sA += c0 * asv[ni][0] + c1 * asv[ni][1];
            dA += c0 * adv[ni][0] + c1 * adv[ni][1];
            sB += c2 * asv[ni][0] + c3 * asv[ni][1];
            dB += c2 * adv[ni][0] + c3 * adv[ni][1];
            long colbase = head * 32 + ni * 8 + 2 * t;
            if (rowA < N) *(__half2*)(hh + (long)rowA * DOUT + colbase) = __floats2half2_rn(c0, c1);
            if (rowB < N) *(__half2*)(hh + (long)rowB * DOUT + colbase) = __floats2half2_rn(c2, c3);
        }
        #pragma unroll
        for (int o = 1; o <= 2; o <<= 1) {
            sA += __shfl_xor_sync(0xffffffffu, sA, o);
            sB += __shfl_xor_sync(0xffffffffu, sB, o);
            dA += __shfl_xor_sync(0xffffffffu, dA, o);
            dB += __shfl_xor_sync(0xffffffffu, dB, o);
        }
        if (t == 0) {
            if (rowA < N) { asrc[rowA * 4 + head] = sA; adst[rowA * 4 + head] = dA; }
            if (rowB < N) { asrc[rowB * 4 + head] = sB; adst[rowB * 4 + head] = dB; }
        }
    }
}

// ---------------------------------------------------------------------------
// CSR build over the E real edges (self loops inline in agg).
__global__ void hist_kernel(const int* __restrict__ ei, int E, int* __restrict__ deg) {
    int i = (blockIdx.x * blockDim.x + threadIdx.x) * 4;
    if (i + 3 < E) {
        int4 d4 = *(const int4*)(ei + E + i);
        atomicAdd(&deg[d4.x], 1);
        atomicAdd(&deg[d4.y], 1);
        atomicAdd(&deg[d4.z], 1);
        atomicAdd(&deg[d4.w], 1);
    } else {
        for (int k = i; k < E; k++) atomicAdd(&deg[ei[E + k]], 1);
    }
}

__global__ void scan_block(const int* __restrict__ deg, int* __restrict__ pre,
                           int* __restrict__ bsum, int N) {
    __shared__ int tmp[2][1024];
    int t = threadIdx.x;
    int gidx = blockIdx.x * 1024 + t;
    int v = (gidx < N) ? deg[gidx] : 0;
    tmp[0][t] = v;
    __syncthreads();
    int pi = 0;
    for (int off = 1; off < 1024; off <<= 1) {
        int val = tmp[pi][t];
        if (t >= off) val += tmp[pi][t - off];
        tmp[pi ^ 1][t] = val;
        pi ^= 1;
        __syncthreads();
    }
    int inc = tmp[pi][t];
    if (gidx < N) pre[gidx] = inc - v;
    if (t == 1023) bsum[blockIdx.x] = inc;
}

__global__ void scan_add_fused(const int* __restrict__ pre, const int* __restrict__ bsum,
                               int* __restrict__ rowptr, int* __restrict__ cursor,
                               int N, int NB) {
    __shared__ int sb[1024];
    int t = threadIdx.x;
    sb[t] = (t < NB) ? bsum[t] : 0;
    __syncthreads();
    for (int off = 1; off < 1024; off <<= 1) {
        int v = sb[t];
        int a = (t >= off) ? sb[t - off] : 0;
        __syncthreads();
        sb[t] = v + a;
        __syncthreads();
    }
    int gidx = blockIdx.x * 1024 + t;
    if (gidx < N) {
        int boff = (blockIdx.x == 0) ? 0 : sb[blockIdx.x - 1];
        int v = pre[gidx] + boff;
        rowptr[gidx] = v;
        cursor[gidx] = v;
    }
}

__global__ void scatter_kernel(const int* __restrict__ ei, int E,
                               int* __restrict__ cursor, int* __restrict__ col) {
    int i = (blockIdx.x * blockDim.x + threadIdx.x) * 4;
    if (i + 3 < E) {
        int4 s4 = *(const int4*)(ei + i);
        int4 d4 = *(const int4*)(ei + E + i);
        int p0 = atomicAdd(&cursor[d4.x], 1);
        int p1 = atomicAdd(&cursor[d4.y], 1);
        int p2 = atomicAdd(&cursor[d4.z], 1);
        int p3 = atomicAdd(&cursor[d4.w], 1);
        col[p0] = s4.x;
        col[p1] = s4.y;
        col[p2] = s4.z;
        col[p3] = s4.w;
    } else {
        for (int k = i; k < E; k++) {
            int pos = atomicAdd(&cursor[ei[E + k]], 1);
            col[pos] = ei[k];
        }
    }
}

// ---------------------------------------------------------------------------
// Fused softmax+aggregate, one warp per dst node, HALF-WARP per edge.
__global__ __launch_bounds__(256)
void agg_kernel(const int* __restrict__ col, const int* __restrict__ rowptr,
                const int* __restrict__ deg,
                const float* __restrict__ asrc, const float* __restrict__ adst,
                const __half* __restrict__ hh, const float* __restrict__ bias,
                float* __restrict__ out, int N) {
    int gtid = blockIdx.x * blockDim.x + threadIdx.x;
    int w = gtid >> 5;
    int lane = threadIdx.x & 31;
    if (w >= N) return;

    int half = lane >> 4;   // 0 or 1
    int L = lane & 15;      // lane within half
    int myhead = L >> 2;    // lane owns features [L*8, L*8+8)

    int start = rowptr[w];
    int cnt = deg[w];
    float adh = __ldg(adst + w * 4 + myhead);

    float acc[8];
    #pragma unroll
    for (int k = 0; k < 8; k++) acc[k] = 0.0f;
    float ssum = 0.0f;

    // Self loop: half 0 only
    if (half == 0) {
        float wgt0 = __expf(lrelu(__ldg(asrc + w * 4 + myhead) + adh));
        ssum = wgt0;
        uint4 raw = *reinterpret_cast<const uint4*>(hh + (long)w * DOUT + L * 8);
        const __half2* h2 = reinterpret_cast<const __half2*>(&raw);
        #pragma unroll
        for (int k = 0; k < 4; k++) {
            float2 f = __half22float2(h2[k]);
            acc[2 * k] = f.x * wgt0;
            acc[2 * k + 1] = f.y * wgt0;
        }
    }

    // Each half processes alternating edges
    #pragma unroll 8
    for (int j = half; j < cnt; j += 2) {
        int src = __ldg(col + start + j);
        float e = lrelu(__ldg(asrc + src * 4 + myhead) + adh);
        float wgt = __expf(e);
        ssum += wgt;
        uint4 raw = *reinterpret_cast<const uint4*>(hh + (long)src * DOUT + L * 8);
        const __half2* h2 = reinterpret_cast<const __half2*>(&raw);
        #pragma unroll
        for (int k = 0; k < 4; k++) {
            float2 f = __half22float2(h2[k]);
            acc[2 * k] = fmaf(f.x, wgt, acc[2 * k]);
            acc[2 * k + 1] = fmaf(f.y, wgt, acc[2 * k + 1]);
        }
    }

    // Merge odd-edge half into even half
    ssum += __shfl_down_sync(0xffffffffu, ssum, 16);
    #pragma unroll
    for (int k = 0; k < 8; k++)
        acc[k] += __shfl_down_sync(0xffffffffu, acc[k], 16);

    if (half == 0) {
        float inv = 1.0f / (ssum + EPS);
        float4 b0 = *(const float4*)(bias + L * 8);
        float4 b1 = *(const float4*)(bias + L * 8 + 4);
        float4 o0 = make_float4(fmaf(acc[0], inv, b0.x), fmaf(acc[1], inv, b0.y),
                                fmaf(acc[2], inv, b0.z), fmaf(acc[3], inv, b0.w));
        float4 o1 = make_float4(fmaf(acc[4], inv, b1.x), fmaf(acc[5], inv, b1.y),
                                fmaf(acc[6], inv, b1.z), fmaf(acc[7], inv, b1.w));
        *(float4*)(out + (long)w * DOUT + L * 8) = o0;
        *(float4*)(out + (long)w * DOUT + L * 8 + 4) = o1;
    }
}

// ---------------------------------------------------------------------------
extern "C" void kernel_launch(void* const* d_in, const int* in_sizes, int n_in,
                              void* d_out, int out_size) {
    const float* x = (const float*)d_in[0];
    const int* ei = (const int*)d_in[1];
    const float* W = (const float*)d_in[2];
    const float* att_src = (const float*)d_in[3];
    const float* att_dst = (const float*)d_in[4];
    const float* bias = (const float*)d_in[5];
    float* out = (float*)d_out;

    int N = in_sizes[0] / DIN;
    int E = in_sizes[1] / 2;
    int NB = (N + 1023) / 1024;
    int E4 = (E + 3) / 4;

    __half* hh;
    float *asrc, *adst;
    int *deg, *pre, *rowptr, *cursor, *bsum, *colp;
    cudaGetSymbolAddress((void**)&hh, g_hh);
    cudaGetSymbolAddress((void**)&asrc, g_asrc);
    cudaGetSymbolAddress((void**)&adst, g_adst);
    cudaGetSymbolAddress((void**)&deg, g_deg);
    cudaGetSymbolAddress((void**)&pre, g_pre);
    cudaGetSymbolAddress((void**)&rowptr, g_rowptr);
    cudaGetSymbolAddress((void**)&cursor, g_cursor);
    cudaGetSymbolAddress((void**)&bsum, g_bsum);
    cudaGetSymbolAddress((void**)&colp, g_col);

    int smem_bytes = 2 * 128 * SMS * sizeof(float);
    cudaFuncSetAttribute(gemm_mma_kernel, cudaFuncAttributeMaxDynamicSharedMemorySize, smem_bytes);

    int thr = 256;

    cudaStream_t s2;
    cudaStreamCreateWithFlags(&s2, cudaStreamNonBlocking);
    cudaEvent_t evFork, evJoin;
    cudaEventCreateWithFlags(&evFork, cudaEventDisableTiming);
    cudaEventCreateWithFlags(&evJoin, cudaEventDisableTiming);

    cudaEventRecord(evFork, 0);
    cudaStreamWaitEvent(s2, evFork, 0);

    // Side stream: CSR build over E edges
    cudaMemsetAsync(deg, 0, N * sizeof(int), s2);
    hist_kernel<<<(E4 + thr - 1) / thr, thr, 0, s2>>>(ei, E, deg);
    scan_block<<<NB, 1024, 0, s2>>>(deg, pre, bsum, N);
    scan_add_fused<<<NB, 1024, 0, s2>>>(pre, bsum, rowptr, cursor, N, NB);
    scatter_kernel<<<(E4 + thr - 1) / thr, thr, 0, s2>>>(ei, E, cursor, colp);
    cudaEventRecord(evJoin, s2);

    // Main stream: GEMM + fused logits (fp16 h output)
    gemm_mma_kernel<<<(N + 127) / 128, 256, smem_bytes>>>(x, W, att_src, att_dst, hh, asrc, adst, N);

    cudaStreamWaitEvent(0, evJoin, 0);
    agg_kernel<<<(N * 32 + thr - 1) / thr, thr>>>(colp, rowptr, deg, asrc, adst, hh, bias, out, N);

    cudaEventDestroy(evFork);
    cudaEventDestroy(evJoin);
    cudaStreamDestroy(s2);
}